// round 14
// baseline (speedup 1.0000x reference)
#include <cuda_runtime.h>
#include <cstdint>
#include <math.h>
#include <math_constants.h>

#define NCTA     128
#define NTHREADS 256
#define HDIM     512
#define TSTEPS   31
#define BSEQ     512
#define OUTC     12
#define NSLOT    513
#define POISON   0xFFFFFFFFu

typedef unsigned long long ull;

// one big buffer, poisoned to 0xFF before every run:
// [h0 rows | h1 rows | scale rows | shift rows]
#define NROW       (TSTEPS * NSLOT)            /* 15903 */
#define OFF_H1     (NROW * HDIM)
#define OFF_SC     (2 * NROW * HDIM)
#define OFF_SH     (OFF_SC + TSTEPS * HDIM)
#define BUF_FLOATS (OFF_SH + TSTEPS * HDIM)    /* ~62.2MB */

__device__ float g_buf[BUF_FLOATS];

// ---- poll-safe loads (asm volatile so they re-issue every loop iteration) ----
__device__ __forceinline__ float4 ldcg4v(const float4* p) {
    float4 v;
    asm volatile("ld.global.cg.v4.f32 {%0,%1,%2,%3}, [%4];"
                 : "=f"(v.x), "=f"(v.y), "=f"(v.z), "=f"(v.w) : "l"(p));
    return v;
}
__device__ __forceinline__ float ldcg1v(const float* p) {
    float v;
    asm volatile("ld.global.cg.f32 %0, [%1];" : "=f"(v) : "l"(p));
    return v;
}
__device__ __forceinline__ bool ok4(float4 v) {
    return (__float_as_uint(v.x) != POISON) & (__float_as_uint(v.y) != POISON) &
           (__float_as_uint(v.z) != POISON) & (__float_as_uint(v.w) != POISON);
}
__device__ __forceinline__ void st_release_gpu_f(float* p, float v) {
    asm volatile("st.release.gpu.global.f32 [%0], %1;" :: "l"(p), "f"(v) : "memory");
}
__device__ __forceinline__ void fence_acq_gpu() {
    asm volatile("fence.acq_rel.gpu;" ::: "memory");
}

// fast activations (rel err ~1e-6)
__device__ __forceinline__ float sigm_f(float x) { return __fdividef(1.0f, 1.0f + __expf(-x)); }
__device__ __forceinline__ float tanh_f(float x) { return 1.0f - __fdividef(2.0f, __expf(2.0f * x) + 1.0f); }

// packed fp32x2 (sm_103a FFMA2 via PTX)
__device__ __forceinline__ ull pk(float x, float y) {
    ull r; asm("mov.b64 %0, {%1, %2};" : "=l"(r) : "f"(x), "f"(y)); return r;
}
__device__ __forceinline__ void upk(ull v, float& x, float& y) {
    asm("mov.b64 {%0, %1}, %2;" : "=f"(x), "=f"(y) : "l"(v));
}
__device__ __forceinline__ void ffma2(ull& d, ull a, ull b) {
    asm("fma.rn.f32x2 %0, %1, %2, %0;" : "+l"(d) : "l"(a), "l"(b));
}

// JAX threefry2x32 (20 rounds)
__device__ __forceinline__ uint2 tf2x32(unsigned k0, unsigned k1, unsigned x0, unsigned x1) {
    unsigned ks2 = k0 ^ k1 ^ 0x1BD11BDAu;
    x0 += k0; x1 += k1;
#define TFR(r) { x0 += x1; x1 = __funnelshift_l(x1, x1, r); x1 ^= x0; }
    TFR(13) TFR(15) TFR(26) TFR(6);  x0 += k1;  x1 += ks2 + 1u;
    TFR(17) TFR(29) TFR(16) TFR(24); x0 += ks2; x1 += k0 + 2u;
    TFR(13) TFR(15) TFR(26) TFR(6);  x0 += k0;  x1 += k1 + 3u;
    TFR(17) TFR(29) TFR(16) TFR(24); x0 += k1;  x1 += ks2 + 4u;
    TFR(13) TFR(15) TFR(26) TFR(6);  x0 += ks2; x1 += k0 + 5u;
#undef TFR
    return make_uint2(x0, x1);
}
__device__ __forceinline__ unsigned rbits_p(unsigned k0, unsigned k1, unsigned m) {
    uint2 p = tf2x32(k0, k1, 0u, m);
    return p.x ^ p.y;
}

// poison the dataflow buffer (kernel node — proven capture-safe pattern)
__global__ void poison_kernel() {
    uint4 pv = make_uint4(POISON, POISON, POISON, POISON);
    uint4* p = (uint4*)g_buf;
    int n = BUF_FLOATS / 4;
    for (int i = blockIdx.x * blockDim.x + threadIdx.x; i < n; i += gridDim.x * blockDim.x)
        p[i] = pv;
}

__global__ void __launch_bounds__(NTHREADS, 1)
net_kernel(const float* __restrict__ Wih0, const float* __restrict__ Whh0,
           const float* __restrict__ b0,   const float* __restrict__ Wih1,
           const float* __restrict__ Whh1, const float* __restrict__ b1,
           const float* __restrict__ gamma,const float* __restrict__ beta,
           const float* __restrict__ Wout, const float* __restrict__ bout,
           const float* __restrict__ h0in, const float* __restrict__ c0in,
           float* __restrict__ out)
{
    __shared__ float grow[4 * HDIM];

    const int tid  = threadIdx.x;
    const int blk  = blockIdx.x;
    const int wid  = tid >> 5;
    const int lane = tid & 31;
    const bool isL0 = (wid < 4);
    const int w    = wid & 3;
    const int col  = blk * 4 + w;

    // ---- register-resident weights, chunk order permuted by (j+blk)&3 ----
    ull wreg[8][4][2];
    {
        const float4* srcA = (const float4*)(isL0 ? Whh0 : Wih1);
#pragma unroll
        for (int r = 0; r < 4; r++) {
            int gr = (r << 9) + col;
#pragma unroll
            for (int j = 0; j < 4; j++) {
                int cc = (j + blk) & 3;
                float4 v = srcA[gr * 128 + cc * 32 + lane];
                wreg[r][j][0] = pk(v.x, v.y);
                wreg[r][j][1] = pk(v.z, v.w);
            }
        }
        if (!isL0) {
            const float4* srcB = (const float4*)Whh1;
#pragma unroll
            for (int r = 0; r < 4; r++) {
                int gr = (r << 9) + col;
#pragma unroll
                for (int j = 0; j < 4; j++) {
                    int cc = (j + blk) & 3;
                    float4 v = srcB[gr * 128 + cc * 32 + lane];
                    wreg[4 + r][j][0] = pk(v.x, v.y);
                    wreg[4 + r][j][1] = pk(v.z, v.w);
                }
            }
        } else {
#pragma unroll
            for (int r = 4; r < 8; r++)
#pragma unroll
                for (int j = 0; j < 4; j++) { wreg[r][j][0] = 0; wreg[r][j][1] = 0; }
        }
    }

    float biasr = 0.0f;
    if (lane < 4) {
        int gr = (lane << 9) + col;
        if (isL0) {
            float s = 0.0f;
            for (int k = 0; k < 64; k++) s += Wih0[gr * 64 + k];   // x == ones
            biasr = s + b0[gr];
        } else {
            biasr = b1[gr];
        }
    }

    float cst = 0.0f;
    if (lane == 0) cst = isL0 ? c0in[col] : c0in[HDIM + col];
    float bnsum = 0.0f, bnssq = 0.0f;

    // carry-in for (iter 0, slot 0)
    if (wid == 0) {
        if (lane < 4)      __stcg(&g_buf[blk * 4 + lane], h0in[blk * 4 + lane]);
        else if (lane < 8) __stcg(&g_buf[OFF_H1 + blk * 4 + lane - 4],
                                  h0in[HDIM + blk * 4 + lane - 4]);
    }

    for (int iter = 0; iter < TSTEPS; ++iter) {
        if (isL0) {
            // ---------------- layer-0 recurrence (runs ahead) ----------------
            for (int k = 0; k < BSEQ; ++k) {
                const float4* h0p = (const float4*)(g_buf + ((size_t)(iter * NSLOT + k) << 9));
                float4 a[4];
                for (;;) {
                    bool ok = true;
#pragma unroll
                    for (int j = 0; j < 4; j++) {
                        int cc = (j + blk) & 3;
                        a[j] = ldcg4v(&h0p[cc * 32 + lane]);
                    }
#pragma unroll
                    for (int j = 0; j < 4; j++) ok &= ok4(a[j]);
                    if (__all_sync(0xffffffffu, ok)) break;
                    __nanosleep(40);
                }
                ull accA[4] = {0, 0, 0, 0}, accB[4] = {0, 0, 0, 0};
#pragma unroll
                for (int j = 0; j < 4; j++) {
                    ull a01 = pk(a[j].x, a[j].y), a23 = pk(a[j].z, a[j].w);
#pragma unroll
                    for (int r = 0; r < 4; r++) {
                        ffma2(accA[r], wreg[r][j][0], a01);
                        ffma2(accB[r], wreg[r][j][1], a23);
                    }
                }
                float s[4];
#pragma unroll
                for (int r = 0; r < 4; r++) {
                    float x0, x1, y0, y1;
                    upk(accA[r], x0, x1); upk(accB[r], y0, y1);
                    s[r] = (x0 + x1) + (y0 + y1);
                }
#pragma unroll
                for (int off = 16; off > 0; off >>= 1)
#pragma unroll
                    for (int r = 0; r < 4; r++) s[r] += __shfl_xor_sync(0xffffffffu, s[r], off);
                float pre = s[0];
                if (lane == 1) pre = s[1];
                else if (lane == 2) pre = s[2];
                else if (lane == 3) pre = s[3];
                pre += biasr;
                float act = (lane == 2) ? tanh_f(pre) : sigm_f(pre);
                float gi = __shfl_sync(0xffffffffu, act, 0);
                float gf = __shfl_sync(0xffffffffu, act, 1);
                float gg = __shfl_sync(0xffffffffu, act, 2);
                float go = __shfl_sync(0xffffffffu, act, 3);
                if (lane == 0) {
                    cst = gf * cst + gi * gg;
                    float hv = go * tanh_f(cst);
                    __stcg(&g_buf[((size_t)(iter * NSLOT + k + 1) << 9) + col], hv);
                    if (k == BSEQ - 1 && iter + 1 < TSTEPS)
                        __stcg(&g_buf[((size_t)((iter + 1) * NSLOT) << 9) + col], hv);
                }
            }

            // ------- phase 3: sentinel poll (sh row) + release/acquire, then compute -------
            {
                int b = blk * 4 + w;
                const float* shp = g_buf + OFF_SH + (iter << 9);
                for (;;) {
                    bool ok = true;
#pragma unroll
                    for (int c = 0; c < 16; c++)
                        ok &= (__float_as_uint(ldcg1v(shp + c * 32 + lane)) != POISON);
                    if (__all_sync(0xffffffffu, ok)) break;
                    __nanosleep(2000);
                }
                fence_acq_gpu();   // sync with each producer's st.release on sh[col]

                const float* yrow = g_buf + OFF_H1 + ((size_t)(iter * NSLOT + b + 1) << 9);
                const float* scp  = g_buf + OFF_SC + (iter << 9);
                float* gr = grow + w * HDIM;
#pragma unroll
                for (int c = 0; c < 16; c++) {
                    int cc = c * 32 + lane;
                    float yn = __ldcg(&yrow[cc]) * __ldcg(&scp[cc]) + __ldcg(&shp[cc]);
                    gr[cc] = expf(-yn * yn);
                }
                __syncwarp();

                float logit = -CUDART_INF_F;
                if (lane < OUTC) {
                    float acc = bout[lane];
                    const float* wrow = Wout + lane * HDIM;
#pragma unroll 8
                    for (int k = 0; k < HDIM; k++) acc += gr[k] * __ldg(wrow + k);
                    logit = acc;
                }

                uint2 kp = tf2x32(0u, 42u, 0u, (unsigned)iter);
                bool full = (iter < 15);

                float v = -CUDART_INF_F;
                int idx = lane;
                bool cand = full ? (lane < 12) : (lane >= 8 && lane < 12);
                if (cand) {
                    unsigned m = full ? (unsigned)(b * 12 + lane) : (unsigned)(b * 4 + (lane - 8));
                    unsigned bits = rbits_p(kp.x, kp.y, m);
                    float u = __uint_as_float((bits >> 9) | 0x3f800000u) - 1.0f;
                    u = fmaxf(u, 1.17549435e-38f);
                    v = -logf(-logf(u)) + logit;
                }
#pragma unroll
                for (int off = 16; off > 0; off >>= 1) {
                    float ov = __shfl_xor_sync(0xffffffffu, v, off);
                    int   oi = __shfl_xor_sync(0xffffffffu, idx, off);
                    if (ov > v || (ov == v && oi < idx)) { v = ov; idx = oi; }
                }
                float lm = logit;
#pragma unroll
                for (int off = 16; off > 0; off >>= 1) lm = fmaxf(lm, __shfl_xor_sync(0xffffffffu, lm, off));
                float e = (lane < OUTC) ? expf(logit - lm) : 0.0f;
#pragma unroll
                for (int off = 16; off > 0; off >>= 1) e += __shfl_xor_sync(0xffffffffu, e, off);
                float la = __shfl_sync(0xffffffffu, logit, idx);
                float lp = la - lm - logf(e);

                if (lane == 0) {
                    out[iter * BSEQ + b]                 = (float)idx;
                    out[TSTEPS * BSEQ + iter * BSEQ + b] = lp;
                }
            }
        } else {
            // ---------------- layer-1 recurrence (critical chain) ----------------
            for (int k = 1; k <= BSEQ; ++k) {
                const float4* h0p = (const float4*)(g_buf + ((size_t)(iter * NSLOT + k) << 9));
                const float4* h1p = (const float4*)(g_buf + OFF_H1 +
                                                    ((size_t)(iter * NSLOT + k - 1) << 9));
                float4 a[4], bb[4];
                for (;;) {
                    bool ok = true;
#pragma unroll
                    for (int j = 0; j < 4; j++) {
                        int cc = (j + blk) & 3;
                        bb[j] = ldcg4v(&h1p[cc * 32 + lane]);
                        a[j]  = ldcg4v(&h0p[cc * 32 + lane]);
                    }
#pragma unroll
                    for (int j = 0; j < 4; j++) ok &= ok4(a[j]) & ok4(bb[j]);
                    if (__all_sync(0xffffffffu, ok)) break;
                    __nanosleep(40);
                }
                ull accA[4] = {0, 0, 0, 0}, accB[4] = {0, 0, 0, 0};
#pragma unroll
                for (int j = 0; j < 4; j++) {
                    ull a01 = pk(a[j].x, a[j].y),  a23 = pk(a[j].z, a[j].w);
                    ull b01 = pk(bb[j].x, bb[j].y), b23 = pk(bb[j].z, bb[j].w);
#pragma unroll
                    for (int r = 0; r < 4; r++) {
                        ffma2(accA[r], wreg[r][j][0], a01);
                        ffma2(accB[r], wreg[r][j][1], a23);
                        ffma2(accA[r], wreg[4 + r][j][0], b01);
                        ffma2(accB[r], wreg[4 + r][j][1], b23);
                    }
                }
                float s[4];
#pragma unroll
                for (int r = 0; r < 4; r++) {
                    float x0, x1, y0, y1;
                    upk(accA[r], x0, x1); upk(accB[r], y0, y1);
                    s[r] = (x0 + x1) + (y0 + y1);
                }
#pragma unroll
                for (int off = 16; off > 0; off >>= 1)
#pragma unroll
                    for (int r = 0; r < 4; r++) s[r] += __shfl_xor_sync(0xffffffffu, s[r], off);
                float pre = s[0];
                if (lane == 1) pre = s[1];
                else if (lane == 2) pre = s[2];
                else if (lane == 3) pre = s[3];
                pre += biasr;
                float act = (lane == 2) ? tanh_f(pre) : sigm_f(pre);
                float gi = __shfl_sync(0xffffffffu, act, 0);
                float gf = __shfl_sync(0xffffffffu, act, 1);
                float gg = __shfl_sync(0xffffffffu, act, 2);
                float go = __shfl_sync(0xffffffffu, act, 3);
                if (lane == 0) {
                    cst = gf * cst + gi * gg;
                    float hv = go * tanh_f(cst);
                    bnsum += hv; bnssq += hv * hv;
                    __stcg(&g_buf[OFF_H1 + ((size_t)(iter * NSLOT + k) << 9) + col], hv);
                    if (k == BSEQ) {
                        if (iter + 1 < TSTEPS)
                            __stcg(&g_buf[OFF_H1 + ((size_t)((iter + 1) * NSLOT) << 9) + col], hv);
                        float mu  = bnsum * (1.0f / 512.0f);
                        float var = bnssq * (1.0f / 512.0f) - mu * mu;
                        float inv = 1.0f / sqrtf(var + 1e-5f);
                        float scv = gamma[col] * inv;
                        __stcg(&g_buf[OFF_SC + (iter << 9) + col], scv);
                        // release store LAST: publishes this thread's h1/sc writes
                        st_release_gpu_f(&g_buf[OFF_SH + (iter << 9) + col],
                                         beta[col] - mu * scv);
                        bnsum = 0.0f; bnssq = 0.0f;
                    }
                }
            }
        }
    }
}

extern "C" void kernel_launch(void* const* d_in, const int* in_sizes, int n_in,
                              void* d_out, int out_size) {
    (void)in_sizes; (void)n_in; (void)out_size;
    const float* Wih0  = (const float*)d_in[0];
    const float* Whh0  = (const float*)d_in[1];
    const float* b0    = (const float*)d_in[2];
    const float* Wih1  = (const float*)d_in[3];
    const float* Whh1  = (const float*)d_in[4];
    const float* b1    = (const float*)d_in[5];
    const float* gamma = (const float*)d_in[6];
    const float* beta  = (const float*)d_in[7];
    const float* Wout  = (const float*)d_in[8];
    const float* bout  = (const float*)d_in[9];
    const float* h0in  = (const float*)d_in[10];
    const float* c0in  = (const float*)d_in[11];
    float* out = (float*)d_out;

    poison_kernel<<<512, 256>>>();
    net_kernel<<<NCTA, NTHREADS>>>(Wih0, Whh0, b0, Wih1, Whh1, b1,
                                   gamma, beta, Wout, bout, h0in, c0in, out);
}

// round 16
// speedup vs baseline: 2.1682x; 2.1682x over previous
#include <cuda_runtime.h>
#include <cstdint>
#include <math.h>
#include <math_constants.h>

#define NCTA     128
#define NTHREADS 256
#define HDIM     512
#define TSTEPS   31
#define BSEQ     512
#define OUTC     12
#define NSLOT    513
#define POISON   0xFFFFFFFFu

typedef unsigned long long ull;

// one big buffer, poisoned to 0xFF before every run:
// [h0 rows | h1 rows | scale rows | shift rows]
#define NROW       (TSTEPS * NSLOT)            /* 15903 */
#define OFF_H1     (NROW * HDIM)
#define OFF_SC     (2 * NROW * HDIM)
#define OFF_SH     (OFF_SC + TSTEPS * HDIM)
#define BUF_FLOATS (OFF_SH + TSTEPS * HDIM)    /* ~62.2MB */

__device__ float g_buf[BUF_FLOATS];

// ---- poll-safe loads (asm volatile so they re-issue every loop iteration) ----
__device__ __forceinline__ float4 ldcg4v(const float4* p) {
    float4 v;
    asm volatile("ld.global.cg.v4.f32 {%0,%1,%2,%3}, [%4];"
                 : "=f"(v.x), "=f"(v.y), "=f"(v.z), "=f"(v.w) : "l"(p));
    return v;
}
__device__ __forceinline__ float ldcg1v(const float* p) {
    float v;
    asm volatile("ld.global.cg.f32 %0, [%1];" : "=f"(v) : "l"(p));
    return v;
}
__device__ __forceinline__ bool ok4(float4 v) {
    return (__float_as_uint(v.x) != POISON) & (__float_as_uint(v.y) != POISON) &
           (__float_as_uint(v.z) != POISON) & (__float_as_uint(v.w) != POISON);
}
__device__ __forceinline__ void st_release_gpu_f(float* p, float v) {
    asm volatile("st.release.gpu.global.f32 [%0], %1;" :: "l"(p), "f"(v) : "memory");
}
__device__ __forceinline__ void fence_acq_gpu() {
    asm volatile("fence.acq_rel.gpu;" ::: "memory");
}

// fast activations (rel err ~1e-6)
__device__ __forceinline__ float sigm_f(float x) { return __fdividef(1.0f, 1.0f + __expf(-x)); }
__device__ __forceinline__ float tanh_f(float x) { return 1.0f - __fdividef(2.0f, __expf(2.0f * x) + 1.0f); }

// packed fp32x2 (sm_103a FFMA2 via PTX)
__device__ __forceinline__ ull pk(float x, float y) {
    ull r; asm("mov.b64 %0, {%1, %2};" : "=l"(r) : "f"(x), "f"(y)); return r;
}
__device__ __forceinline__ void upk(ull v, float& x, float& y) {
    asm("mov.b64 {%0, %1}, %2;" : "=f"(x), "=f"(y) : "l"(v));
}
__device__ __forceinline__ void ffma2(ull& d, ull a, ull b) {
    asm("fma.rn.f32x2 %0, %1, %2, %0;" : "+l"(d) : "l"(a), "l"(b));
}

// JAX threefry2x32 (20 rounds)
__device__ __forceinline__ uint2 tf2x32(unsigned k0, unsigned k1, unsigned x0, unsigned x1) {
    unsigned ks2 = k0 ^ k1 ^ 0x1BD11BDAu;
    x0 += k0; x1 += k1;
#define TFR(r) { x0 += x1; x1 = __funnelshift_l(x1, x1, r); x1 ^= x0; }
    TFR(13) TFR(15) TFR(26) TFR(6);  x0 += k1;  x1 += ks2 + 1u;
    TFR(17) TFR(29) TFR(16) TFR(24); x0 += ks2; x1 += k0 + 2u;
    TFR(13) TFR(15) TFR(26) TFR(6);  x0 += k0;  x1 += k1 + 3u;
    TFR(17) TFR(29) TFR(16) TFR(24); x0 += k1;  x1 += ks2 + 4u;
    TFR(13) TFR(15) TFR(26) TFR(6);  x0 += ks2; x1 += k0 + 5u;
#undef TFR
    return make_uint2(x0, x1);
}
__device__ __forceinline__ unsigned rbits_p(unsigned k0, unsigned k1, unsigned m) {
    uint2 p = tf2x32(k0, k1, 0u, m);
    return p.x ^ p.y;
}

// poison the dataflow buffer (kernel node — capture-safe)
__global__ void poison_kernel() {
    uint4 pv = make_uint4(POISON, POISON, POISON, POISON);
    uint4* p = (uint4*)g_buf;
    int n = BUF_FLOATS / 4;
    for (int i = blockIdx.x * blockDim.x + threadIdx.x; i < n; i += gridDim.x * blockDim.x)
        p[i] = pv;
}

__global__ void __launch_bounds__(NTHREADS, 1)
net_kernel(const float* __restrict__ Wih0, const float* __restrict__ Whh0,
           const float* __restrict__ b0,   const float* __restrict__ Wih1,
           const float* __restrict__ Whh1, const float* __restrict__ b1,
           const float* __restrict__ gamma,const float* __restrict__ beta,
           const float* __restrict__ Wout, const float* __restrict__ bout,
           const float* __restrict__ h0in, const float* __restrict__ c0in,
           float* __restrict__ out)
{
    __shared__ float grow[4 * HDIM];

    const int tid  = threadIdx.x;
    const int blk  = blockIdx.x;
    const int wid  = tid >> 5;
    const int lane = tid & 31;
    const bool isL0 = (wid < 4);
    const int w    = wid & 3;
    const int col  = blk * 4 + w;

    // ---- register-resident weights, chunk order permuted by (j+blk)&3 ----
    // L0 warps: rows 0..3 = Whh0 gates (i,f,g,o); L1: rows 0..3 = Wih1, 4..7 = Whh1
    ull wreg[8][4][2];
    {
        const float4* srcA = (const float4*)(isL0 ? Whh0 : Wih1);
#pragma unroll
        for (int r = 0; r < 4; r++) {
            int gr = (r << 9) + col;
#pragma unroll
            for (int j = 0; j < 4; j++) {
                int cc = (j + blk) & 3;
                float4 v = srcA[gr * 128 + cc * 32 + lane];
                wreg[r][j][0] = pk(v.x, v.y);
                wreg[r][j][1] = pk(v.z, v.w);
            }
        }
        if (!isL0) {
            const float4* srcB = (const float4*)Whh1;
#pragma unroll
            for (int r = 0; r < 4; r++) {
                int gr = (r << 9) + col;
#pragma unroll
                for (int j = 0; j < 4; j++) {
                    int cc = (j + blk) & 3;
                    float4 v = srcB[gr * 128 + cc * 32 + lane];
                    wreg[4 + r][j][0] = pk(v.x, v.y);
                    wreg[4 + r][j][1] = pk(v.z, v.w);
                }
            }
        } else {
#pragma unroll
            for (int r = 4; r < 8; r++)
#pragma unroll
                for (int j = 0; j < 4; j++) { wreg[r][j][0] = 0; wreg[r][j][1] = 0; }
        }
    }

    float biasr = 0.0f;
    if (lane < 4) {
        int gr = (lane << 9) + col;
        if (isL0) {
            float s = 0.0f;
            for (int k = 0; k < 64; k++) s += Wih0[gr * 64 + k];   // x == ones
            biasr = s + b0[gr];
        } else {
            biasr = b1[gr];
        }
    }

    float cst = 0.0f;
    if (lane == 0) cst = isL0 ? c0in[col] : c0in[HDIM + col];
    float bnsum = 0.0f, bnssq = 0.0f;

    // carry-in for (iter 0, slot 0)
    if (wid == 0) {
        if (lane < 4)      __stcg(&g_buf[blk * 4 + lane], h0in[blk * 4 + lane]);
        else if (lane < 8) __stcg(&g_buf[OFF_H1 + blk * 4 + lane - 4],
                                  h0in[HDIM + blk * 4 + lane - 4]);
    }

    for (int iter = 0; iter < TSTEPS; ++iter) {
        // ---- lockstep rounds: warp 0 polls, all other warps parked at syncthreads ----
        for (int k = 0; k <= BSEQ; ++k) {
            if (wid == 0) {
                // poll h0 row [iter, k] and (k>=1) h1 row [iter, k-1]
                const float4* r0 = (const float4*)(g_buf + ((size_t)(iter * NSLOT + k) << 9));
                size_t i1 = (k >= 1) ? (size_t)(iter * NSLOT + k - 1) : 0;
                const float4* r1 = (const float4*)(g_buf + OFF_H1 + (i1 << 9));
                const bool needh1 = (k >= 1);
                int tries = 0;
                for (;;) {
                    bool ok = true;
#pragma unroll
                    for (int j = 0; j < 4; j++) ok &= ok4(ldcg4v(r0 + j * 32 + lane));
                    if (needh1) {
#pragma unroll
                        for (int j = 0; j < 4; j++) ok &= ok4(ldcg4v(r1 + j * 32 + lane));
                    }
                    if (__all_sync(0xffffffffu, ok)) break;
                    if (++tries > 256) __nanosleep(200);   // guard only; normally unreached
                }
            }
            __syncthreads();   // releases compute warps; also compiler memory barrier

            const bool active = isL0 ? (k < BSEQ) : (k >= 1);
            if (active) {
                const float4* h0p = (const float4*)(g_buf + ((size_t)(iter * NSLOT + k) << 9));
                ull accA[4] = {0, 0, 0, 0}, accB[4] = {0, 0, 0, 0};
#pragma unroll
                for (int j = 0; j < 4; j++) {
                    int cc = (j + blk) & 3;
                    float4 a = __ldcg(&h0p[cc * 32 + lane]);
                    ull a01 = pk(a.x, a.y), a23 = pk(a.z, a.w);
#pragma unroll
                    for (int r = 0; r < 4; r++) {
                        ffma2(accA[r], wreg[r][j][0], a01);
                        ffma2(accB[r], wreg[r][j][1], a23);
                    }
                }
                if (!isL0) {
                    const float4* h1p = (const float4*)(g_buf + OFF_H1 +
                                                        ((size_t)(iter * NSLOT + k - 1) << 9));
#pragma unroll
                    for (int j = 0; j < 4; j++) {
                        int cc = (j + blk) & 3;
                        float4 b = __ldcg(&h1p[cc * 32 + lane]);
                        ull b01 = pk(b.x, b.y), b23 = pk(b.z, b.w);
#pragma unroll
                        for (int r = 0; r < 4; r++) {
                            ffma2(accA[r], wreg[4 + r][j][0], b01);
                            ffma2(accB[r], wreg[4 + r][j][1], b23);
                        }
                    }
                }
                float s[4];
#pragma unroll
                for (int r = 0; r < 4; r++) {
                    float x0, x1, y0, y1;
                    upk(accA[r], x0, x1); upk(accB[r], y0, y1);
                    s[r] = (x0 + x1) + (y0 + y1);
                }
#pragma unroll
                for (int off = 16; off > 0; off >>= 1)
#pragma unroll
                    for (int r = 0; r < 4; r++) s[r] += __shfl_xor_sync(0xffffffffu, s[r], off);
                float pre = s[0];
                if (lane == 1) pre = s[1];
                else if (lane == 2) pre = s[2];
                else if (lane == 3) pre = s[3];
                pre += biasr;
                float act = (lane == 2) ? tanh_f(pre) : sigm_f(pre);
                float gi = __shfl_sync(0xffffffffu, act, 0);
                float gf = __shfl_sync(0xffffffffu, act, 1);
                float gg = __shfl_sync(0xffffffffu, act, 2);
                float go = __shfl_sync(0xffffffffu, act, 3);
                if (lane == 0) {
                    cst = gf * cst + gi * gg;
                    float hv = go * tanh_f(cst);
                    if (isL0) {
                        __stcg(&g_buf[((size_t)(iter * NSLOT + k + 1) << 9) + col], hv);
                        if (k == BSEQ - 1 && iter + 1 < TSTEPS)
                            __stcg(&g_buf[((size_t)((iter + 1) * NSLOT) << 9) + col], hv);
                    } else {
                        bnsum += hv; bnssq += hv * hv;
                        __stcg(&g_buf[OFF_H1 + ((size_t)(iter * NSLOT + k) << 9) + col], hv);
                        if (k == BSEQ) {
                            if (iter + 1 < TSTEPS)
                                __stcg(&g_buf[OFF_H1 + ((size_t)((iter + 1) * NSLOT) << 9) + col], hv);
                            float mu  = bnsum * (1.0f / 512.0f);
                            float var = bnssq * (1.0f / 512.0f) - mu * mu;
                            float inv = 1.0f / sqrtf(var + 1e-5f);
                            float scv = gamma[col] * inv;
                            __stcg(&g_buf[OFF_SC + (iter << 9) + col], scv);
                            // release LAST: publishes this thread's h1/sc writes
                            st_release_gpu_f(&g_buf[OFF_SH + (iter << 9) + col],
                                             beta[col] - mu * scv);
                            bnsum = 0.0f; bnssq = 0.0f;
                        }
                    }
                }
            }
        }

        // ------- phase 3 (L0 warps): sentinel poll + release/acquire, then sample -------
        if (isL0) {
            int b = blk * 4 + w;
            const float* shp = g_buf + OFF_SH + (iter << 9);
            for (;;) {
                bool ok = true;
#pragma unroll
                for (int c = 0; c < 16; c++)
                    ok &= (__float_as_uint(ldcg1v(shp + c * 32 + lane)) != POISON);
                if (__all_sync(0xffffffffu, ok)) break;
                __nanosleep(2000);
            }
            fence_acq_gpu();   // pairs with producers' st.release on sh[col]

            const float* yrow = g_buf + OFF_H1 + ((size_t)(iter * NSLOT + b + 1) << 9);
            const float* scp  = g_buf + OFF_SC + (iter << 9);
            float* gr = grow + w * HDIM;
#pragma unroll
            for (int c = 0; c < 16; c++) {
                int cc = c * 32 + lane;
                float yn = __ldcg(&yrow[cc]) * __ldcg(&scp[cc]) + __ldcg(&shp[cc]);
                gr[cc] = expf(-yn * yn);
            }
            __syncwarp();

            float logit = -CUDART_INF_F;
            if (lane < OUTC) {
                float acc = bout[lane];
                const float* wrow = Wout + lane * HDIM;
#pragma unroll 8
                for (int k = 0; k < HDIM; k++) acc += gr[k] * __ldg(wrow + k);
                logit = acc;
            }

            uint2 kp = tf2x32(0u, 42u, 0u, (unsigned)iter);
            bool full = (iter < 15);

            float v = -CUDART_INF_F;
            int idx = lane;
            bool cand = full ? (lane < 12) : (lane >= 8 && lane < 12);
            if (cand) {
                unsigned m = full ? (unsigned)(b * 12 + lane) : (unsigned)(b * 4 + (lane - 8));
                unsigned bits = rbits_p(kp.x, kp.y, m);
                float u = __uint_as_float((bits >> 9) | 0x3f800000u) - 1.0f;
                u = fmaxf(u, 1.17549435e-38f);
                v = -logf(-logf(u)) + logit;
            }
#pragma unroll
            for (int off = 16; off > 0; off >>= 1) {
                float ov = __shfl_xor_sync(0xffffffffu, v, off);
                int   oi = __shfl_xor_sync(0xffffffffu, idx, off);
                if (ov > v || (ov == v && oi < idx)) { v = ov; idx = oi; }
            }
            float lm = logit;
#pragma unroll
            for (int off = 16; off > 0; off >>= 1) lm = fmaxf(lm, __shfl_xor_sync(0xffffffffu, lm, off));
            float e = (lane < OUTC) ? expf(logit - lm) : 0.0f;
#pragma unroll
            for (int off = 16; off > 0; off >>= 1) e += __shfl_xor_sync(0xffffffffu, e, off);
            float la = __shfl_sync(0xffffffffu, logit, idx);
            float lp = la - lm - logf(e);

            if (lane == 0) {
                out[iter * BSEQ + b]                 = (float)idx;
                out[TSTEPS * BSEQ + iter * BSEQ + b] = lp;
            }
        }
        // L1 warps proceed to next iter and park at its first __syncthreads
    }
}

extern "C" void kernel_launch(void* const* d_in, const int* in_sizes, int n_in,
                              void* d_out, int out_size) {
    (void)in_sizes; (void)n_in; (void)out_size;
    const float* Wih0  = (const float*)d_in[0];
    const float* Whh0  = (const float*)d_in[1];
    const float* b0    = (const float*)d_in[2];
    const float* Wih1  = (const float*)d_in[3];
    const float* Whh1  = (const float*)d_in[4];
    const float* b1    = (const float*)d_in[5];
    const float* gamma = (const float*)d_in[6];
    const float* beta  = (const float*)d_in[7];
    const float* Wout  = (const float*)d_in[8];
    const float* bout  = (const float*)d_in[9];
    const float* h0in  = (const float*)d_in[10];
    const float* c0in  = (const float*)d_in[11];
    float* out = (float*)d_out;

    poison_kernel<<<512, 256>>>();
    net_kernel<<<NCTA, NTHREADS>>>(Wih0, Whh0, b0, Wih1, Whh1, b1,
                                   gamma, beta, Wout, bout, h0in, c0in, out);
}